// round 1
// baseline (speedup 1.0000x reference)
#include <cuda_runtime.h>
#include <math.h>

// Problem dims
#define Bn 2
#define Tn 2048
#define Cn 1024
#define Hn 16
#define HDn 64
#define Mrows (Bn * Tn)   // 4096

// Scratch (allocation-free: __device__ globals)
__device__ float g_q[Bn * Hn * Tn * HDn];  // [B,H,T,64], pre-scaled by 1/8
__device__ float g_k[Bn * Hn * Tn * HDn];
__device__ float g_v[Bn * Hn * Tn * HDn];
__device__ float g_a[Bn * Tn * Cn];        // attention output, [B*T, C]

// ---------------------------------------------------------------------------
// SGEMM: D = (A @ W^T + bias) * scale
//   A: [M, K] row-major, W: [N, K] row-major (torch Linear weight), K=N=1024
//   MODE 0: scatter into head layout [B,H,T,64]
//   MODE 1: plain row-major [M, N]
// Tiles: BM=BN=128, BK=8, 256 threads, 8x8 per thread.
// ---------------------------------------------------------------------------
template <int MODE>
__global__ __launch_bounds__(256)
void sgemm_kernel(const float* __restrict__ A, const float* __restrict__ W,
                  const float* __restrict__ bias, float* __restrict__ D,
                  float scale)
{
    const int K = Cn;
    __shared__ float As[8][128];
    __shared__ float Bs[8][128];

    const int tid = threadIdx.x;
    const int m0 = blockIdx.y * 128;
    const int n0 = blockIdx.x * 128;

    const int lr = tid >> 1;          // 0..127: row within tile to load
    const int lk = (tid & 1) * 4;     // 0 or 4: k-offset of this thread's float4

    const float* Aptr = A + (size_t)(m0 + lr) * K + lk;
    const float* Wptr = W + (size_t)(n0 + lr) * K + lk;

    const int tx = tid & 15;          // 0..15
    const int ty = tid >> 4;          // 0..15

    float acc[8][8];
#pragma unroll
    for (int i = 0; i < 8; i++)
#pragma unroll
        for (int j = 0; j < 8; j++) acc[i][j] = 0.0f;

    for (int k0 = 0; k0 < K; k0 += 8) {
        float4 av = *(const float4*)(Aptr + k0);
        float4 wv = *(const float4*)(Wptr + k0);
        As[lk + 0][lr] = av.x; As[lk + 1][lr] = av.y;
        As[lk + 2][lr] = av.z; As[lk + 3][lr] = av.w;
        Bs[lk + 0][lr] = wv.x; Bs[lk + 1][lr] = wv.y;
        Bs[lk + 2][lr] = wv.z; Bs[lk + 3][lr] = wv.w;
        __syncthreads();

#pragma unroll
        for (int kk = 0; kk < 8; kk++) {
            float4 a0 = *(const float4*)&As[kk][ty * 4];
            float4 a1 = *(const float4*)&As[kk][64 + ty * 4];
            float4 b0 = *(const float4*)&Bs[kk][tx * 4];
            float4 b1 = *(const float4*)&Bs[kk][64 + tx * 4];
            float ra[8] = {a0.x, a0.y, a0.z, a0.w, a1.x, a1.y, a1.z, a1.w};
            float rb[8] = {b0.x, b0.y, b0.z, b0.w, b1.x, b1.y, b1.z, b1.w};
#pragma unroll
            for (int i = 0; i < 8; i++)
#pragma unroll
                for (int j = 0; j < 8; j++)
                    acc[i][j] = fmaf(ra[i], rb[j], acc[i][j]);
        }
        __syncthreads();
    }

    // Epilogue
#pragma unroll
    for (int i = 0; i < 8; i++) {
        int gr = m0 + ty * 4 + (i & 3) + ((i >= 4) ? 64 : 0);
#pragma unroll
        for (int j = 0; j < 8; j++) {
            int gc = n0 + tx * 4 + (j & 3) + ((j >= 4) ? 64 : 0);
            float v = (acc[i][j] + bias[gc]) * scale;
            if (MODE == 0) {
                int b = gr / Tn, t = gr % Tn;
                int h = gc >> 6, d = gc & 63;
                D[(((size_t)(b * Hn + h)) * Tn + t) * HDn + d] = v;
            } else {
                D[(size_t)gr * Cn + gc] = v;
            }
        }
    }
}

// ---------------------------------------------------------------------------
// Flash attention (causal), fp32.
//   Q/K/V: [B*H, T, 64], Q pre-scaled.
//   Block: 128 threads, 1 query row per thread. K/V tiles of 64 rows in smem.
//   Output: [B*T, C] row-major for the projection GEMM.
// ---------------------------------------------------------------------------
__global__ __launch_bounds__(128)
void flash_kernel(const float* __restrict__ Qg, const float* __restrict__ Kg,
                  const float* __restrict__ Vg, float* __restrict__ Ob)
{
    __shared__ float Ksh[64 * 64];
    __shared__ float Vsh[64 * 64];

    const int bh = blockIdx.y;            // 0..31
    const int qt = blockIdx.x;            // 0..15 (128-row q tiles)
    const int tid = threadIdx.x;          // 0..127
    const int r = qt * 128 + tid;         // this thread's query row

    const float* qptr = Qg + ((size_t)bh * Tn + r) * HDn;
    float q[64];
#pragma unroll
    for (int i = 0; i < 16; i++) {
        float4 v = *(const float4*)(qptr + i * 4);
        q[i * 4 + 0] = v.x; q[i * 4 + 1] = v.y;
        q[i * 4 + 2] = v.z; q[i * 4 + 3] = v.w;
    }

    float o[64];
#pragma unroll
    for (int d = 0; d < 64; d++) o[d] = 0.0f;
    float mval = -1e30f, lsum = 0.0f;

    const float* Kbh = Kg + (size_t)bh * Tn * HDn;
    const float* Vbh = Vg + (size_t)bh * Tn * HDn;

    const int ktend = 2 * qt + 1;   // last k-tile index touching this q tile
    for (int kt = 0; kt <= ktend; kt++) {
        __syncthreads();
        // Cooperative load of K and V tiles: 4096 contiguous floats each
        const float* ksrc = Kbh + (size_t)kt * 64 * HDn;
        const float* vsrc = Vbh + (size_t)kt * 64 * HDn;
#pragma unroll
        for (int i = 0; i < 8; i++) {
            int idx = i * 512 + tid * 4;
            *(float4*)&Ksh[idx] = *(const float4*)(ksrc + idx);
            *(float4*)&Vsh[idx] = *(const float4*)(vsrc + idx);
        }
        __syncthreads();

        const int kbase = kt * 64;
        float s[64];
#pragma unroll
        for (int c = 0; c < 64; c++) {
            float acc = 0.0f;
#pragma unroll
            for (int d = 0; d < 64; d += 4) {
                float4 kv = *(const float4*)&Ksh[c * 64 + d];
                acc = fmaf(q[d + 0], kv.x, acc);
                acc = fmaf(q[d + 1], kv.y, acc);
                acc = fmaf(q[d + 2], kv.z, acc);
                acc = fmaf(q[d + 3], kv.w, acc);
            }
            s[c] = acc;
        }

        // Causal mask (only partially/fully-masked tiles need it)
        if (kbase + 63 > r) {
#pragma unroll
            for (int c = 0; c < 64; c++)
                if (kbase + c > r) s[c] = -1e30f;
        }

        // Online softmax
        float tm = mval;
#pragma unroll
        for (int c = 0; c < 64; c++) tm = fmaxf(tm, s[c]);
        float corr = __expf(mval - tm);
        mval = tm;
        lsum *= corr;
#pragma unroll
        for (int d = 0; d < 64; d++) o[d] *= corr;

#pragma unroll
        for (int c = 0; c < 64; c++) {
            float p = __expf(s[c] - mval);
            lsum += p;
#pragma unroll
            for (int d = 0; d < 64; d += 4) {
                float4 vv = *(const float4*)&Vsh[c * 64 + d];
                o[d + 0] = fmaf(p, vv.x, o[d + 0]);
                o[d + 1] = fmaf(p, vv.y, o[d + 1]);
                o[d + 2] = fmaf(p, vv.z, o[d + 2]);
                o[d + 3] = fmaf(p, vv.w, o[d + 3]);
            }
        }
    }

    const float inv = 1.0f / lsum;
    const int b = bh / Hn, h = bh % Hn;
    float* dst = Ob + ((size_t)b * Tn + r) * Cn + h * HDn;
#pragma unroll
    for (int d = 0; d < 64; d += 4) {
        float4 v;
        v.x = o[d + 0] * inv; v.y = o[d + 1] * inv;
        v.z = o[d + 2] * inv; v.w = o[d + 3] * inv;
        *(float4*)(dst + d) = v;
    }
}

// ---------------------------------------------------------------------------
extern "C" void kernel_launch(void* const* d_in, const int* in_sizes, int n_in,
                              void* d_out, int out_size)
{
    const float* x  = (const float*)d_in[0];
    const float* Wq = (const float*)d_in[1];
    const float* bq = (const float*)d_in[2];
    const float* Wk = (const float*)d_in[3];
    const float* bk = (const float*)d_in[4];
    const float* Wv = (const float*)d_in[5];
    const float* bv = (const float*)d_in[6];
    const float* Wp = (const float*)d_in[7];
    const float* bp = (const float*)d_in[8];
    float* out = (float*)d_out;

    float *pq, *pk, *pv, *pa;
    cudaGetSymbolAddress((void**)&pq, g_q);
    cudaGetSymbolAddress((void**)&pk, g_k);
    cudaGetSymbolAddress((void**)&pv, g_v);
    cudaGetSymbolAddress((void**)&pa, g_a);

    dim3 gg(Cn / 128, Mrows / 128);  // (8, 32)
    const float qscale = 1.0f / 8.0f;  // 1/sqrt(64)

    sgemm_kernel<0><<<gg, 256>>>(x, Wq, bq, pq, qscale);
    sgemm_kernel<0><<<gg, 256>>>(x, Wk, bk, pk, 1.0f);
    sgemm_kernel<0><<<gg, 256>>>(x, Wv, bv, pv, 1.0f);

    dim3 fg(Tn / 128, Bn * Hn);      // (16, 32)
    flash_kernel<<<fg, 128>>>(pq, pk, pv, pa);

    sgemm_kernel<1><<<gg, 256>>>(pa, Wp, bp, out, 1.0f);
}

// round 2
// speedup vs baseline: 1.6676x; 1.6676x over previous
#include <cuda_runtime.h>
#include <math.h>
#include <stdint.h>

// Problem dims
#define Bn 2
#define Tn 2048
#define Cn 1024
#define Hn 16
#define HDn 64
#define Mrows (Bn * Tn)   // 4096

// Scratch (allocation-free: __device__ globals)
__device__ float g_q[Bn * Hn * Tn * HDn];  // [B,H,T,64], pre-scaled by 1/8
__device__ float g_k[Bn * Hn * Tn * HDn];
__device__ float g_v[Bn * Hn * Tn * HDn];
__device__ float g_a[Bn * Tn * Cn];        // attention output, [B*T, C]

__device__ __forceinline__ uint32_t f2tf32(float x) {
    uint32_t y;
    asm("cvt.rna.tf32.f32 %0, %1;" : "=r"(y) : "f"(x));
    return y;
}

// ---------------------------------------------------------------------------
// tf32 tensor-core GEMM: D = (A @ W^T + bias) * scale
//   A: [M, 1024] row-major fp32, W: [1024, 1024] row-major (torch Linear).
//   BM=BN=128, BK=16, 256 threads (8 warps), warp tile 64x32 via m16n8k8 tf32.
//   Double-buffered smem, PAD=20 words/row for conflict-free fragment loads.
//   MODE 0: scatter into head layout [B,H,T,64];  MODE 1: row-major [M, N].
// ---------------------------------------------------------------------------
#define GPAD 20

template <int MODE>
__global__ __launch_bounds__(256)
void tf32_gemm(const float* __restrict__ A, const float* __restrict__ W,
               const float* __restrict__ bias, float* __restrict__ D,
               float scale)
{
    __shared__ uint32_t As[2][128 * GPAD];
    __shared__ uint32_t Bs[2][128 * GPAD];

    const int tid  = threadIdx.x;
    const int m0   = blockIdx.y * 128;
    const int n0   = blockIdx.x * 128;
    const int lane = tid & 31;
    const int wid  = tid >> 5;
    const int wm   = (wid & 1) * 64;   // warp M offset
    const int wn   = (wid >> 1) * 32;  // warp N offset
    const int grp  = lane >> 2;
    const int tig  = lane & 3;

    // global load mapping: 2 float4 per array per thread
    const int lr = tid >> 2;           // 0..63
    const int lc = (tid & 3) * 4;      // 0,4,8,12
    const float* Ap = A + (size_t)(m0 + lr) * Cn + lc;
    const float* Wp = W + (size_t)(n0 + lr) * Cn + lc;

    float acc[4][4][4];
#pragma unroll
    for (int i = 0; i < 4; i++)
#pragma unroll
        for (int j = 0; j < 4; j++)
#pragma unroll
            for (int v = 0; v < 4; v++) acc[i][j][v] = 0.0f;

    // prologue: tile 0 -> buffer 0
    {
        float4 a0 = *(const float4*)(Ap);
        float4 a1 = *(const float4*)(Ap + (size_t)64 * Cn);
        float4 b0 = *(const float4*)(Wp);
        float4 b1 = *(const float4*)(Wp + (size_t)64 * Cn);
        uint4 ua0 = {f2tf32(a0.x), f2tf32(a0.y), f2tf32(a0.z), f2tf32(a0.w)};
        uint4 ua1 = {f2tf32(a1.x), f2tf32(a1.y), f2tf32(a1.z), f2tf32(a1.w)};
        uint4 ub0 = {f2tf32(b0.x), f2tf32(b0.y), f2tf32(b0.z), f2tf32(b0.w)};
        uint4 ub1 = {f2tf32(b1.x), f2tf32(b1.y), f2tf32(b1.z), f2tf32(b1.w)};
        *(uint4*)&As[0][lr * GPAD + lc]        = ua0;
        *(uint4*)&As[0][(lr + 64) * GPAD + lc] = ua1;
        *(uint4*)&Bs[0][lr * GPAD + lc]        = ub0;
        *(uint4*)&Bs[0][(lr + 64) * GPAD + lc] = ub1;
    }
    __syncthreads();

    for (int it = 0; it < 64; it++) {
        const int cur = it & 1;
        float4 a0, a1, b0, b1;
        if (it < 63) {
            const float* Ap2 = Ap + (it + 1) * 16;
            const float* Wp2 = Wp + (it + 1) * 16;
            a0 = *(const float4*)(Ap2);
            a1 = *(const float4*)(Ap2 + (size_t)64 * Cn);
            b0 = *(const float4*)(Wp2);
            b1 = *(const float4*)(Wp2 + (size_t)64 * Cn);
        }

        // compute from buffer cur
#pragma unroll
        for (int ks = 0; ks < 2; ks++) {
            const int k0 = ks * 8;
            uint32_t af[4][4];
            uint32_t bf[4][2];
#pragma unroll
            for (int mt = 0; mt < 4; mt++) {
                const uint32_t* base = &As[cur][(wm + mt * 16 + grp) * GPAD + k0 + tig];
                af[mt][0] = base[0];
                af[mt][1] = base[8 * GPAD];
                af[mt][2] = base[4];
                af[mt][3] = base[8 * GPAD + 4];
            }
#pragma unroll
            for (int nt = 0; nt < 4; nt++) {
                const uint32_t* base = &Bs[cur][(wn + nt * 8 + grp) * GPAD + k0 + tig];
                bf[nt][0] = base[0];
                bf[nt][1] = base[4];
            }
#pragma unroll
            for (int mt = 0; mt < 4; mt++)
#pragma unroll
                for (int nt = 0; nt < 4; nt++) {
                    asm volatile(
                        "mma.sync.aligned.m16n8k8.row.col.f32.tf32.tf32.f32 "
                        "{%0,%1,%2,%3}, {%4,%5,%6,%7}, {%8,%9}, {%0,%1,%2,%3};"
                        : "+f"(acc[mt][nt][0]), "+f"(acc[mt][nt][1]),
                          "+f"(acc[mt][nt][2]), "+f"(acc[mt][nt][3])
                        : "r"(af[mt][0]), "r"(af[mt][1]), "r"(af[mt][2]), "r"(af[mt][3]),
                          "r"(bf[nt][0]), "r"(bf[nt][1]));
                }
        }

        if (it < 63) {
            const int nxt = cur ^ 1;
            uint4 ua0 = {f2tf32(a0.x), f2tf32(a0.y), f2tf32(a0.z), f2tf32(a0.w)};
            uint4 ua1 = {f2tf32(a1.x), f2tf32(a1.y), f2tf32(a1.z), f2tf32(a1.w)};
            uint4 ub0 = {f2tf32(b0.x), f2tf32(b0.y), f2tf32(b0.z), f2tf32(b0.w)};
            uint4 ub1 = {f2tf32(b1.x), f2tf32(b1.y), f2tf32(b1.z), f2tf32(b1.w)};
            *(uint4*)&As[nxt][lr * GPAD + lc]        = ua0;
            *(uint4*)&As[nxt][(lr + 64) * GPAD + lc] = ua1;
            *(uint4*)&Bs[nxt][lr * GPAD + lc]        = ub0;
            *(uint4*)&Bs[nxt][(lr + 64) * GPAD + lc] = ub1;
        }
        __syncthreads();
    }

    // epilogue
#pragma unroll
    for (int mt = 0; mt < 4; mt++) {
        const int r0 = m0 + wm + mt * 16 + grp;
#pragma unroll
        for (int nt = 0; nt < 4; nt++) {
            const int c0 = n0 + wn + nt * 8 + tig * 2;
#pragma unroll
            for (int v = 0; v < 4; v++) {
                const int gr = r0 + ((v >= 2) ? 8 : 0);
                const int gc = c0 + (v & 1);
                const float val = (acc[mt][nt][v] + bias[gc]) * scale;
                if (MODE == 0) {
                    const int b = gr / Tn, t = gr % Tn;
                    const int h = gc >> 6, d = gc & 63;
                    D[(((size_t)(b * Hn + h)) * Tn + t) * HDn + d] = val;
                } else {
                    D[(size_t)gr * Cn + gc] = val;
                }
            }
        }
    }
}

// ---------------------------------------------------------------------------
// Flash attention (causal), fp32, low-register version.
//   1 query row per thread, 128 threads/block. K/V tiles of 64 rows in smem.
//   Scores processed in chunks of 16 columns (s[16] in regs -> no spills).
//   Per-warp causal chunk skipping.
// ---------------------------------------------------------------------------
__global__ __launch_bounds__(128)
void flash_kernel(const float* __restrict__ Qg, const float* __restrict__ Kg,
                  const float* __restrict__ Vg, float* __restrict__ Ob)
{
    __shared__ float Ksh[64 * 64];
    __shared__ float Vsh[64 * 64];

    const int bh  = blockIdx.y;           // 0..31
    const int qt  = blockIdx.x;           // 0..15
    const int tid = threadIdx.x;          // 0..127
    const int r   = qt * 128 + tid;
    const int warp_max_r = qt * 128 + ((tid >> 5) << 5) + 31;

    const float* qptr = Qg + ((size_t)bh * Tn + r) * HDn;
    float q[64];
#pragma unroll
    for (int i = 0; i < 16; i++) {
        float4 v = *(const float4*)(qptr + i * 4);
        q[i * 4 + 0] = v.x; q[i * 4 + 1] = v.y;
        q[i * 4 + 2] = v.z; q[i * 4 + 3] = v.w;
    }

    float o[64];
#pragma unroll
    for (int d = 0; d < 64; d++) o[d] = 0.0f;
    float mval = -1e30f, lsum = 0.0f;

    const float* Kbh = Kg + (size_t)bh * Tn * HDn;
    const float* Vbh = Vg + (size_t)bh * Tn * HDn;

    const int ktend = 2 * qt + 1;
    for (int kt = 0; kt <= ktend; kt++) {
        __syncthreads();
        const float* ksrc = Kbh + (size_t)kt * 64 * HDn;
        const float* vsrc = Vbh + (size_t)kt * 64 * HDn;
#pragma unroll
        for (int i = 0; i < 8; i++) {
            int idx = i * 512 + tid * 4;
            *(float4*)&Ksh[idx] = *(const float4*)(ksrc + idx);
            *(float4*)&Vsh[idx] = *(const float4*)(vsrc + idx);
        }
        __syncthreads();

        const int kb0 = kt * 64;
        int nch = (warp_max_r >= kb0 + 63) ? 4 : ((warp_max_r - kb0) / 16 + 1);
        if (nch < 0) nch = 0;

        for (int ch = 0; ch < nch; ch++) {
            const int kbase = kb0 + ch * 16;
            float s[16];
#pragma unroll
            for (int c = 0; c < 16; c++) {
                const float* krow = &Ksh[(ch * 16 + c) * 64];
                float acc = 0.0f;
#pragma unroll
                for (int d = 0; d < 64; d += 4) {
                    float4 kv = *(const float4*)(krow + d);
                    acc = fmaf(q[d + 0], kv.x, acc);
                    acc = fmaf(q[d + 1], kv.y, acc);
                    acc = fmaf(q[d + 2], kv.z, acc);
                    acc = fmaf(q[d + 3], kv.w, acc);
                }
                s[c] = acc;
            }

            if (kbase + 15 > r) {
#pragma unroll
                for (int c = 0; c < 16; c++)
                    if (kbase + c > r) s[c] = -1e30f;
            }

            float nm = mval;
#pragma unroll
            for (int c = 0; c < 16; c++) nm = fmaxf(nm, s[c]);
            const float corr = __expf(mval - nm);
            mval = nm;
            lsum *= corr;
#pragma unroll
            for (int d = 0; d < 64; d++) o[d] *= corr;

#pragma unroll
            for (int c = 0; c < 16; c++) {
                const float p = __expf(s[c] - mval);
                lsum += p;
                const float* vrow = &Vsh[(ch * 16 + c) * 64];
#pragma unroll
                for (int d = 0; d < 64; d += 4) {
                    float4 vv = *(const float4*)(vrow + d);
                    o[d + 0] = fmaf(p, vv.x, o[d + 0]);
                    o[d + 1] = fmaf(p, vv.y, o[d + 1]);
                    o[d + 2] = fmaf(p, vv.z, o[d + 2]);
                    o[d + 3] = fmaf(p, vv.w, o[d + 3]);
                }
            }
        }
    }

    const float inv = 1.0f / lsum;
    const int b = bh / Hn, h = bh % Hn;
    float* dst = Ob + ((size_t)b * Tn + r) * Cn + h * HDn;
#pragma unroll
    for (int d = 0; d < 64; d += 4) {
        float4 v;
        v.x = o[d + 0] * inv; v.y = o[d + 1] * inv;
        v.z = o[d + 2] * inv; v.w = o[d + 3] * inv;
        *(float4*)(dst + d) = v;
    }
}

// ---------------------------------------------------------------------------
extern "C" void kernel_launch(void* const* d_in, const int* in_sizes, int n_in,
                              void* d_out, int out_size)
{
    const float* x  = (const float*)d_in[0];
    const float* Wq = (const float*)d_in[1];
    const float* bq = (const float*)d_in[2];
    const float* Wk = (const float*)d_in[3];
    const float* bk = (const float*)d_in[4];
    const float* Wv = (const float*)d_in[5];
    const float* bv = (const float*)d_in[6];
    const float* Wp = (const float*)d_in[7];
    const float* bp = (const float*)d_in[8];
    float* out = (float*)d_out;

    float *pq, *pk, *pv, *pa;
    cudaGetSymbolAddress((void**)&pq, g_q);
    cudaGetSymbolAddress((void**)&pk, g_k);
    cudaGetSymbolAddress((void**)&pv, g_v);
    cudaGetSymbolAddress((void**)&pa, g_a);

    dim3 gg(Cn / 128, Mrows / 128);  // (8, 32)
    const float qscale = 1.0f / 8.0f;

    tf32_gemm<0><<<gg, 256>>>(x, Wq, bq, pq, qscale);
    tf32_gemm<0><<<gg, 256>>>(x, Wk, bk, pk, 1.0f);
    tf32_gemm<0><<<gg, 256>>>(x, Wv, bv, pv, 1.0f);

    dim3 fg(Tn / 128, Bn * Hn);      // (16, 32)
    flash_kernel<<<fg, 128>>>(pq, pk, pv, pa);

    tf32_gemm<1><<<gg, 256>>>(pa, Wp, bp, out, 1.0f);
}

// round 3
// speedup vs baseline: 4.3795x; 2.6263x over previous
#include <cuda_runtime.h>
#include <math.h>
#include <stdint.h>

// Problem dims
#define Bn 2
#define Tn 2048
#define Cn 1024
#define Hn 16
#define HDn 64
#define Mrows (Bn * Tn)   // 4096

// Scratch (allocation-free: __device__ globals)
__device__ float g_q[Bn * Hn * Tn * HDn];  // [B,H,T,64], pre-scaled by 1/8
__device__ float g_k[Bn * Hn * Tn * HDn];
__device__ float g_v[Bn * Hn * Tn * HDn];
__device__ float g_a[Bn * Tn * Cn];        // attention output, [B*T, C]

__device__ __forceinline__ uint32_t f2tf32(float x) {
    uint32_t y;
    asm("cvt.rna.tf32.f32 %0, %1;" : "=r"(y) : "f"(x));
    return y;
}

__device__ __forceinline__ void mma_tf32(float* c, const uint32_t* a,
                                         uint32_t b0, uint32_t b1) {
    asm volatile(
        "mma.sync.aligned.m16n8k8.row.col.f32.tf32.tf32.f32 "
        "{%0,%1,%2,%3}, {%4,%5,%6,%7}, {%8,%9}, {%0,%1,%2,%3};"
        : "+f"(c[0]), "+f"(c[1]), "+f"(c[2]), "+f"(c[3])
        : "r"(a[0]), "r"(a[1]), "r"(a[2]), "r"(a[3]), "r"(b0), "r"(b1));
}

// ---------------------------------------------------------------------------
// tf32 tensor-core GEMM: D = (A @ W^T + bias) * scale   (unchanged from R2)
// ---------------------------------------------------------------------------
#define GPAD 20

template <int MODE>
__global__ __launch_bounds__(256)
void tf32_gemm(const float* __restrict__ A, const float* __restrict__ W,
               const float* __restrict__ bias, float* __restrict__ D,
               float scale)
{
    __shared__ uint32_t As[2][128 * GPAD];
    __shared__ uint32_t Bs[2][128 * GPAD];

    const int tid  = threadIdx.x;
    const int m0   = blockIdx.y * 128;
    const int n0   = blockIdx.x * 128;
    const int lane = tid & 31;
    const int wid  = tid >> 5;
    const int wm   = (wid & 1) * 64;
    const int wn   = (wid >> 1) * 32;
    const int grp  = lane >> 2;
    const int tig  = lane & 3;

    const int lr = tid >> 2;
    const int lc = (tid & 3) * 4;
    const float* Ap = A + (size_t)(m0 + lr) * Cn + lc;
    const float* Wp = W + (size_t)(n0 + lr) * Cn + lc;

    float acc[4][4][4];
#pragma unroll
    for (int i = 0; i < 4; i++)
#pragma unroll
        for (int j = 0; j < 4; j++)
#pragma unroll
            for (int v = 0; v < 4; v++) acc[i][j][v] = 0.0f;

    {
        float4 a0 = *(const float4*)(Ap);
        float4 a1 = *(const float4*)(Ap + (size_t)64 * Cn);
        float4 b0 = *(const float4*)(Wp);
        float4 b1 = *(const float4*)(Wp + (size_t)64 * Cn);
        uint4 ua0 = {f2tf32(a0.x), f2tf32(a0.y), f2tf32(a0.z), f2tf32(a0.w)};
        uint4 ua1 = {f2tf32(a1.x), f2tf32(a1.y), f2tf32(a1.z), f2tf32(a1.w)};
        uint4 ub0 = {f2tf32(b0.x), f2tf32(b0.y), f2tf32(b0.z), f2tf32(b0.w)};
        uint4 ub1 = {f2tf32(b1.x), f2tf32(b1.y), f2tf32(b1.z), f2tf32(b1.w)};
        *(uint4*)&As[0][lr * GPAD + lc]        = ua0;
        *(uint4*)&As[0][(lr + 64) * GPAD + lc] = ua1;
        *(uint4*)&Bs[0][lr * GPAD + lc]        = ub0;
        *(uint4*)&Bs[0][(lr + 64) * GPAD + lc] = ub1;
    }
    __syncthreads();

    for (int it = 0; it < 64; it++) {
        const int cur = it & 1;
        float4 a0, a1, b0, b1;
        if (it < 63) {
            const float* Ap2 = Ap + (it + 1) * 16;
            const float* Wp2 = Wp + (it + 1) * 16;
            a0 = *(const float4*)(Ap2);
            a1 = *(const float4*)(Ap2 + (size_t)64 * Cn);
            b0 = *(const float4*)(Wp2);
            b1 = *(const float4*)(Wp2 + (size_t)64 * Cn);
        }

#pragma unroll
        for (int ks = 0; ks < 2; ks++) {
            const int k0 = ks * 8;
            uint32_t af[4][4];
            uint32_t bf[4][2];
#pragma unroll
            for (int mt = 0; mt < 4; mt++) {
                const uint32_t* base = &As[cur][(wm + mt * 16 + grp) * GPAD + k0 + tig];
                af[mt][0] = base[0];
                af[mt][1] = base[8 * GPAD];
                af[mt][2] = base[4];
                af[mt][3] = base[8 * GPAD + 4];
            }
#pragma unroll
            for (int nt = 0; nt < 4; nt++) {
                const uint32_t* base = &Bs[cur][(wn + nt * 8 + grp) * GPAD + k0 + tig];
                bf[nt][0] = base[0];
                bf[nt][1] = base[4];
            }
#pragma unroll
            for (int mt = 0; mt < 4; mt++)
#pragma unroll
                for (int nt = 0; nt < 4; nt++)
                    mma_tf32(acc[mt][nt], af[mt], bf[nt][0], bf[nt][1]);
        }

        if (it < 63) {
            const int nxt = cur ^ 1;
            uint4 ua0 = {f2tf32(a0.x), f2tf32(a0.y), f2tf32(a0.z), f2tf32(a0.w)};
            uint4 ua1 = {f2tf32(a1.x), f2tf32(a1.y), f2tf32(a1.z), f2tf32(a1.w)};
            uint4 ub0 = {f2tf32(b0.x), f2tf32(b0.y), f2tf32(b0.z), f2tf32(b0.w)};
            uint4 ub1 = {f2tf32(b1.x), f2tf32(b1.y), f2tf32(b1.z), f2tf32(b1.w)};
            *(uint4*)&As[nxt][lr * GPAD + lc]        = ua0;
            *(uint4*)&As[nxt][(lr + 64) * GPAD + lc] = ua1;
            *(uint4*)&Bs[nxt][lr * GPAD + lc]        = ub0;
            *(uint4*)&Bs[nxt][(lr + 64) * GPAD + lc] = ub1;
        }
        __syncthreads();
    }

#pragma unroll
    for (int mt = 0; mt < 4; mt++) {
        const int r0 = m0 + wm + mt * 16 + grp;
#pragma unroll
        for (int nt = 0; nt < 4; nt++) {
            const int c0 = n0 + wn + nt * 8 + tig * 2;
#pragma unroll
            for (int v = 0; v < 4; v++) {
                const int gr = r0 + ((v >= 2) ? 8 : 0);
                const int gc = c0 + (v & 1);
                const float val = (acc[mt][nt][v] + bias[gc]) * scale;
                if (MODE == 0) {
                    const int b = gr / Tn, t = gr % Tn;
                    const int h = gc >> 6, d = gc & 63;
                    D[(((size_t)(b * Hn + h)) * Tn + t) * HDn + d] = val;
                } else {
                    D[(size_t)gr * Cn + gc] = val;
                }
            }
        }
    }
}

// ---------------------------------------------------------------------------
// Tensor-core flash attention (causal), tf32 mma.
//   Block: 256 threads (8 warps), 128 q-rows (16 per warp). K/V tile = 64 keys.
//   S = Q K^T via m16n8k8; online softmax in fragments; P staged in smem
//   (reuses Q buffer, per-warp private); O += P V via m16n8k8.
//   Smem strides: Q/P/K = 68 (conflict-free row-frag loads),
//                 V = 72 (conflict-free column-frag loads).
// ---------------------------------------------------------------------------
#define SQP 68
#define SV  72
#define FLASH_SMEM ((128 * SQP + 64 * SQP + 64 * SV) * 4)

__global__ __launch_bounds__(256)
void flash_tc(const float* __restrict__ Qg, const float* __restrict__ Kg,
              const float* __restrict__ Vg, float* __restrict__ Ob)
{
    extern __shared__ uint32_t sh[];
    uint32_t* Qs = sh;                    // 128 x (stride 68) : Q, then P
    uint32_t* Ks = sh + 128 * SQP;        // 64 x (stride 68)
    uint32_t* Vs = sh + 128 * SQP + 64 * SQP;  // 64 x (stride 72)

    const int bh  = blockIdx.y;           // 0..31
    const int qt  = blockIdx.x;           // 0..15
    const int tid = threadIdx.x;
    const int lane = tid & 31;
    const int wid  = tid >> 5;            // 0..7
    const int grp  = lane >> 2;           // 0..7
    const int tig  = lane & 3;            // 0..3
    const int q0   = qt * 128;
    const int w0   = wid * 16;            // warp's q-row offset in block

    // ---- stage Q (tf32) ----
    const float* qsrc = Qg + ((size_t)bh * Tn + q0) * HDn;
    for (int i = tid; i < 128 * 16; i += 256) {
        const int row = i >> 4, c4 = (i & 15) * 4;
        float4 v = *(const float4*)(qsrc + row * 64 + c4);
        uint32_t* d = &Qs[row * SQP + c4];
        d[0] = f2tf32(v.x); d[1] = f2tf32(v.y);
        d[2] = f2tf32(v.z); d[3] = f2tf32(v.w);
    }
    __syncthreads();

    // ---- extract Q fragments (held in regs for whole kernel) ----
    uint32_t aq[8][4];
#pragma unroll
    for (int k = 0; k < 8; k++) {
        aq[k][0] = Qs[(w0 + grp) * SQP + k * 8 + tig];
        aq[k][1] = Qs[(w0 + grp + 8) * SQP + k * 8 + tig];
        aq[k][2] = Qs[(w0 + grp) * SQP + k * 8 + tig + 4];
        aq[k][3] = Qs[(w0 + grp + 8) * SQP + k * 8 + tig + 4];
    }
    __syncthreads();   // Qs now reusable as P

    float o[8][4];
#pragma unroll
    for (int n = 0; n < 8; n++)
#pragma unroll
        for (int v = 0; v < 4; v++) o[n][v] = 0.0f;
    float m0r = -1e30f, m1r = -1e30f, l0 = 0.0f, l1 = 0.0f;

    const float* Kbh = Kg + (size_t)bh * Tn * HDn;
    const float* Vbh = Vg + (size_t)bh * Tn * HDn;

    const int row0 = q0 + w0 + grp;
    const int row1 = row0 + 8;
    const int nkt = 2 * qt + 2;

    for (int kt = 0; kt < nkt; kt++) {
        __syncthreads();   // previous tile's reads done before overwrite
        const float* ks = Kbh + (size_t)kt * 64 * HDn;
        const float* vs = Vbh + (size_t)kt * 64 * HDn;
        for (int i = tid; i < 64 * 16; i += 256) {
            const int row = i >> 4, c4 = (i & 15) * 4;
            float4 kv = *(const float4*)(ks + row * 64 + c4);
            float4 vv = *(const float4*)(vs + row * 64 + c4);
            uint32_t* dk = &Ks[row * SQP + c4];
            dk[0] = f2tf32(kv.x); dk[1] = f2tf32(kv.y);
            dk[2] = f2tf32(kv.z); dk[3] = f2tf32(kv.w);
            uint32_t* dv = &Vs[row * SV + c4];
            dv[0] = f2tf32(vv.x); dv[1] = f2tf32(vv.y);
            dv[2] = f2tf32(vv.z); dv[3] = f2tf32(vv.w);
        }
        __syncthreads();

        const int kb = kt * 64;
        const bool active = (kb <= q0 + w0 + 15);   // warp has unmasked cols
        if (active) {
            // ---- S = Q K^T ----
            float s[8][4];
#pragma unroll
            for (int n = 0; n < 8; n++)
#pragma unroll
                for (int v = 0; v < 4; v++) s[n][v] = 0.0f;
#pragma unroll
            for (int k = 0; k < 8; k++) {
#pragma unroll
                for (int n = 0; n < 8; n++) {
                    const uint32_t* kp = &Ks[(n * 8 + grp) * SQP + k * 8 + tig];
                    mma_tf32(s[n], aq[k], kp[0], kp[4]);
                }
            }

            // ---- causal mask ----
            if (kb + 63 > row0) {
#pragma unroll
                for (int n = 0; n < 8; n++) {
                    const int col = kb + n * 8 + tig * 2;
                    if (col > row0)     s[n][0] = -1e30f;
                    if (col + 1 > row0) s[n][1] = -1e30f;
                    if (col > row1)     s[n][2] = -1e30f;
                    if (col + 1 > row1) s[n][3] = -1e30f;
                }
            }

            // ---- online softmax ----
            float tm0 = -1e30f, tm1 = -1e30f;
#pragma unroll
            for (int n = 0; n < 8; n++) {
                tm0 = fmaxf(tm0, fmaxf(s[n][0], s[n][1]));
                tm1 = fmaxf(tm1, fmaxf(s[n][2], s[n][3]));
            }
            tm0 = fmaxf(tm0, __shfl_xor_sync(0xffffffff, tm0, 1));
            tm0 = fmaxf(tm0, __shfl_xor_sync(0xffffffff, tm0, 2));
            tm1 = fmaxf(tm1, __shfl_xor_sync(0xffffffff, tm1, 1));
            tm1 = fmaxf(tm1, __shfl_xor_sync(0xffffffff, tm1, 2));

            const float nm0 = fmaxf(m0r, tm0);
            const float nm1 = fmaxf(m1r, tm1);
            const float c0 = __expf(m0r - nm0);
            const float c1 = __expf(m1r - nm1);
            m0r = nm0; m1r = nm1;

            float ps0 = 0.0f, ps1 = 0.0f;
            uint32_t* p0row = &Qs[(w0 + grp) * SQP];
            uint32_t* p1row = &Qs[(w0 + grp + 8) * SQP];
#pragma unroll
            for (int n = 0; n < 8; n++) {
                const float e0 = __expf(s[n][0] - nm0);
                const float e1 = __expf(s[n][1] - nm0);
                const float e2 = __expf(s[n][2] - nm1);
                const float e3 = __expf(s[n][3] - nm1);
                ps0 += e0 + e1;
                ps1 += e2 + e3;
                const int c = n * 8 + tig * 2;
                p0row[c]     = f2tf32(e0);
                p0row[c + 1] = f2tf32(e1);
                p1row[c]     = f2tf32(e2);
                p1row[c + 1] = f2tf32(e3);
            }
            ps0 += __shfl_xor_sync(0xffffffff, ps0, 1);
            ps0 += __shfl_xor_sync(0xffffffff, ps0, 2);
            ps1 += __shfl_xor_sync(0xffffffff, ps1, 1);
            ps1 += __shfl_xor_sync(0xffffffff, ps1, 2);
            l0 = l0 * c0 + ps0;
            l1 = l1 * c1 + ps1;

#pragma unroll
            for (int n = 0; n < 8; n++) {
                o[n][0] *= c0; o[n][1] *= c0;
                o[n][2] *= c1; o[n][3] *= c1;
            }
            __syncwarp();

            // ---- O += P V ----
#pragma unroll
            for (int k = 0; k < 8; k++) {
                uint32_t ap[4];
                ap[0] = Qs[(w0 + grp) * SQP + k * 8 + tig];
                ap[1] = Qs[(w0 + grp + 8) * SQP + k * 8 + tig];
                ap[2] = Qs[(w0 + grp) * SQP + k * 8 + tig + 4];
                ap[3] = Qs[(w0 + grp + 8) * SQP + k * 8 + tig + 4];
#pragma unroll
                for (int n = 0; n < 8; n++) {
                    const uint32_t b0 = Vs[(k * 8 + tig) * SV + n * 8 + grp];
                    const uint32_t b1 = Vs[(k * 8 + tig + 4) * SV + n * 8 + grp];
                    mma_tf32(o[n], ap, b0, b1);
                }
            }
            __syncwarp();
        }
    }

    // ---- epilogue ----
    const float inv0 = 1.0f / l0;
    const float inv1 = 1.0f / l1;
    const int b = bh / Hn, h = bh % Hn;
    float* dst0 = Ob + ((size_t)(b * Tn) + row0) * Cn + h * HDn;
    float* dst1 = dst0 + (size_t)8 * Cn;
#pragma unroll
    for (int n = 0; n < 8; n++) {
        const int c = n * 8 + tig * 2;
        dst0[c]     = o[n][0] * inv0;
        dst0[c + 1] = o[n][1] * inv0;
        dst1[c]     = o[n][2] * inv1;
        dst1[c + 1] = o[n][3] * inv1;
    }
}

// ---------------------------------------------------------------------------
extern "C" void kernel_launch(void* const* d_in, const int* in_sizes, int n_in,
                              void* d_out, int out_size)
{
    const float* x  = (const float*)d_in[0];
    const float* Wq = (const float*)d_in[1];
    const float* bq = (const float*)d_in[2];
    const float* Wk = (const float*)d_in[3];
    const float* bk = (const float*)d_in[4];
    const float* Wv = (const float*)d_in[5];
    const float* bv = (const float*)d_in[6];
    const float* Wp = (const float*)d_in[7];
    const float* bp = (const float*)d_in[8];
    float* out = (float*)d_out;

    float *pq, *pk, *pv, *pa;
    cudaGetSymbolAddress((void**)&pq, g_q);
    cudaGetSymbolAddress((void**)&pk, g_k);
    cudaGetSymbolAddress((void**)&pv, g_v);
    cudaGetSymbolAddress((void**)&pa, g_a);

    dim3 gg(Cn / 128, Mrows / 128);  // (8, 32)
    const float qscale = 1.0f / 8.0f;

    tf32_gemm<0><<<gg, 256>>>(x, Wq, bq, pq, qscale);
    tf32_gemm<0><<<gg, 256>>>(x, Wk, bk, pk, 1.0f);
    tf32_gemm<0><<<gg, 256>>>(x, Wv, bv, pv, 1.0f);

    static bool attr_set = false;
    if (!attr_set) {
        cudaFuncSetAttribute(flash_tc,
                             cudaFuncAttributeMaxDynamicSharedMemorySize,
                             FLASH_SMEM);
        attr_set = true;
    }
    dim3 fg(Tn / 128, Bn * Hn);      // (16, 32)
    flash_tc<<<fg, 256, FLASH_SMEM>>>(pq, pk, pv, pa);

    tf32_gemm<1><<<gg, 256>>>(pa, Wp, bp, out, 1.0f);
}